// round 11
// baseline (speedup 1.0000x reference)
#include <cuda_runtime.h>
#include <cuda_bf16.h>
#include <cstdint>

typedef unsigned long long u64;

// ---------------------------------------------------------------------------
// Tensor-core helpers (baseline PTX: ldmatrix sm_75+, mma.sync sm_80+)
// ---------------------------------------------------------------------------
__device__ __forceinline__ uint32_t smem_u32(const void* p) {
    uint32_t a;
    asm("{ .reg .u64 t; cvta.to.shared.u64 t, %1; cvt.u32.u64 %0, t; }" : "=r"(a) : "l"(p));
    return a;
}

#define LDSM_X4(r0, r1, r2, r3, a) \
    asm volatile("ldmatrix.sync.aligned.m8n8.x4.shared.b16 {%0,%1,%2,%3}, [%4];" \
        : "=r"(r0), "=r"(r1), "=r"(r2), "=r"(r3) : "r"(a))
#define LDSM_X4T(r0, r1, r2, r3, a) \
    asm volatile("ldmatrix.sync.aligned.m8n8.x4.trans.shared.b16 {%0,%1,%2,%3}, [%4];" \
        : "=r"(r0), "=r"(r1), "=r"(r2), "=r"(r3) : "r"(a))

__device__ __forceinline__ void mma16816(float* d, const uint32_t* a,
                                         uint32_t b0, uint32_t b1) {
    asm volatile(
        "mma.sync.aligned.m16n8k16.row.col.f32.bf16.bf16.f32 "
        "{%0,%1,%2,%3}, {%4,%5,%6,%7}, {%8,%9}, {%0,%1,%2,%3};"
        : "+f"(d[0]), "+f"(d[1]), "+f"(d[2]), "+f"(d[3])
        : "r"(a[0]), "r"(a[1]), "r"(a[2]), "r"(a[3]), "r"(b0), "r"(b1));
}

__device__ __forceinline__ void bsplit16(float v, unsigned short& h, unsigned short& l) {
    __nv_bfloat16 bh = __float2bfloat16_rn(v);
    __nv_bfloat16 bl = __float2bfloat16_rn(v - __bfloat162float(bh));
    h = __bfloat16_as_ushort(bh);
    l = __bfloat16_as_ushort(bl);
}

// split v -> (hi16 << 16) | lo16 packed u32
__device__ __forceinline__ uint32_t bsplit_u32(float v) {
    __nv_bfloat16 bh = __float2bfloat16_rn(v);
    __nv_bfloat16 bl = __float2bfloat16_rn(v - __bfloat162float(bh));
    return ((uint32_t)__bfloat16_as_ushort(bh) << 16) | (uint32_t)__bfloat16_as_ushort(bl);
}

__device__ __forceinline__ uint32_t bsplit_pack_hi(float v0, float v1, uint32_t& lo) {
    __nv_bfloat16 h0 = __float2bfloat16_rn(v0);
    __nv_bfloat16 h1 = __float2bfloat16_rn(v1);
    __nv_bfloat16 l0 = __float2bfloat16_rn(v0 - __bfloat162float(h0));
    __nv_bfloat16 l1 = __float2bfloat16_rn(v1 - __bfloat162float(h1));
    lo = (uint32_t)__bfloat16_as_ushort(l0) | ((uint32_t)__bfloat16_as_ushort(l1) << 16);
    return (uint32_t)__bfloat16_as_ushort(h0) | ((uint32_t)__bfloat16_as_ushort(h1) << 16);
}

__device__ __forceinline__ uint32_t prmt(uint32_t a, uint32_t b, uint32_t sel) {
    uint32_t d;
    asm("prmt.b32 %0, %1, %2, %3;" : "=r"(d) : "r"(a), "r"(b), "r"(sel));
    return d;
}

#define STS128(a, r0, r1, r2, r3) \
    asm volatile("st.shared.v4.b32 [%0], {%1,%2,%3,%4};" :: "r"(a), "r"(r0), "r"(r1), "r"(r2), "r"(r3) : "memory")

// swizzle: flip the 16B slot when bit7 set -> 8 consecutive w pixels (32B
// stride) occupy 8 distinct 16B slots => ldmatrix conflict-free.
#define SWZ(a) ((a) ^ (((a) >> 3) & 0x10))

// ---------------------------------------------------------------------------
// Scratch.  g_y holds u32-packed (bf16 hi | bf16 lo) per element.
// ---------------------------------------------------------------------------
static __device__ float g_Wm[64 * 64];
static __device__ uint32_t g_y[512u * 16u * 62u * 62u];

// ---------------------------------------------------------------------------
// Kernel 1: tensor-core conv. grid = 512 images x 4 row-strips (+1 Wm block).
// 512 thr = 16 warps; warp = one output row (16-row strips, 18-row halo).
// Epilogue now splits acc -> packed u32 (hi|lo bf16) before storing to g_y.
// ---------------------------------------------------------------------------
static constexpr int A_HI = 0;          // 18 * 2176 = 39168
static constexpr int A_LO = 39168;      // 39168
static constexpr int B_SM = 78336;      // 9 * 512 * 2 = 9216
static constexpr int SM_CONV = 87552;

__global__ __launch_bounds__(512) void conv_tc_kernel(const float* __restrict__ x,
                                                      const float* __restrict__ ker,
                                                      const float* __restrict__ c0p,
                                                      const float* __restrict__ c1p,
                                                      const float* __restrict__ c2p) {
    extern __shared__ __align__(128) char smem[];
    uint32_t sb = smem_u32(smem);
    int tid = threadIdx.x;

    if (blockIdx.x == 2048) {
        // ---- TT-matrix reconstruction (hidden under the conv wave) ----
        float* s0 = reinterpret_cast<float*>(smem);
        float* s1 = s0 + 128;
        float* s2 = s1 + 1024;
        for (int i = tid; i < 128; i += 512) s0[i] = c0p[i];
        for (int i = tid; i < 1024; i += 512) s1[i] = c1p[i];
        for (int i = tid; i < 128; i += 512) s2[i] = c2p[i];
        __syncthreads();
        for (int e = tid; e < 4096; e += 512) {
            int i = e >> 6, j = e & 63;
            int i1 = i >> 4, i2 = (i >> 2) & 3, i3 = i & 3;
            int j1 = j >> 4, j2 = (j >> 2) & 3, j3 = j & 3;
            float s = 0.f;
            #pragma unroll
            for (int r1 = 0; r1 < 8; ++r1) {
                float a = s0[(i1 * 4 + j1) * 8 + r1];
                float t = 0.f;
                #pragma unroll
                for (int r2 = 0; r2 < 8; ++r2)
                    t += s1[((r1 * 4 + i2) * 4 + j2) * 8 + r2] * s2[(r2 * 4 + i3) * 4 + j3];
                s = fmaf(a, t, s);
            }
            g_Wm[e] = s;
        }
        return;
    }

    int bi = blockIdx.x >> 2;
    int strip = blockIdx.x & 3;
    int r0 = strip * 16;

    // zero ONLY the w=64..67 pad slots (both buffers, 18 rows)
    for (int idx = tid; idx < 288; idx += 512) {
        int bsel  = idx & 1;
        int chunk = (idx >> 1) & 1;
        int w  = 64 + ((idx >> 2) & 3);
        int rr = idx >> 4;                 // 0..17
        uint32_t raw = (uint32_t)rr * 2176 + w * 32 + chunk * 16;
        uint32_t a = SWZ(raw) + (bsel ? A_LO : A_HI);
        STS128(sb + a, 0u, 0u, 0u, 0u);
    }

    // B fill: ker flat [co][cin][kh][kw] -> [tap][cin][co] hi/lo, swizzled
    for (int idx = tid; idx < 2304; idx += 512) {
        int co = idx / 144, rem = idx % 144;
        int cin = rem / 9, kk = rem % 9;
        unsigned short h, l;
        bsplit16(ker[idx], h, l);
        uint32_t raw = (uint32_t)kk * 512 + cin * 32 + co * 2;
        uint32_t sw = SWZ(raw);
        *reinterpret_cast<unsigned short*>(smem + B_SM + sw) = h;
        *reinterpret_cast<unsigned short*>(smem + B_SM + 4608 + sw) = l;
    }

    // A fill: thread = (row, w); pack 16 cin -> 2x STS.128 per buffer.
    const float* xb = x + (size_t)bi * (16 * 64 * 64);
    for (int idx = tid; idx < 1152; idx += 512) {
        int w  = idx & 63;
        int rr = idx >> 6;                 // 0..17
        int rg = r0 + rr; if (rg > 63) rg = 63;
        const float* src = xb + rg * 64 + w;
        uint32_t ph[8], pl[8];
        #pragma unroll
        for (int e = 0; e < 8; ++e) {
            float v0 = src[(size_t)(2 * e) * 4096];
            float v1 = src[(size_t)(2 * e + 1) * 4096];
            ph[e] = bsplit_pack_hi(v0, v1, pl[e]);
        }
        uint32_t raw0 = (uint32_t)rr * 2176 + w * 32;
        uint32_t a0 = SWZ(raw0);
        uint32_t a1 = SWZ(raw0 + 16);
        STS128(sb + A_HI + a0, ph[0], ph[1], ph[2], ph[3]);
        STS128(sb + A_HI + a1, ph[4], ph[5], ph[6], ph[7]);
        STS128(sb + A_LO + a0, pl[0], pl[1], pl[2], pl[3]);
        STS128(sb + A_LO + a1, pl[4], pl[5], pl[6], pl[7]);
    }
    __syncthreads();

    int lane = tid & 31;
    int warp = tid >> 5;          // output row within strip (0..15)
    int h = r0 + warp;

    float acc[4][2][4];
    #pragma unroll
    for (int wt = 0; wt < 4; ++wt)
        #pragma unroll
        for (int f = 0; f < 2; ++f)
            #pragma unroll
            for (int e = 0; e < 4; ++e) acc[wt][f][e] = 0.f;

    int arow = lane & 15;
    int khalf = (lane >> 4) * 16;

    #pragma unroll
    for (int kh = 0; kh < 3; ++kh) {
        #pragma unroll
        for (int kw = 0; kw < 3; ++kw) {
            int tap = kh * 3 + kw;
            uint32_t brw = (uint32_t)tap * 512 + arow * 32 + khalf;
            uint32_t baddr = sb + B_SM + SWZ(brw);
            uint32_t bh[4], bl[4];
            LDSM_X4T(bh[0], bh[1], bh[2], bh[3], baddr);
            LDSM_X4T(bl[0], bl[1], bl[2], bl[3], baddr + 4608);

            uint32_t rbase = (uint32_t)(warp + kh) * 2176;
            #pragma unroll
            for (int wt = 0; wt < 4; ++wt) {
                uint32_t araw = rbase + (wt * 16 + arow + kw) * 32 + khalf;
                uint32_t aaddr = sb + SWZ(araw);
                uint32_t ahi[4], alo[4];
                LDSM_X4(ahi[0], ahi[1], ahi[2], ahi[3], aaddr + A_HI);
                LDSM_X4(alo[0], alo[1], alo[2], alo[3], aaddr + A_LO);
                #pragma unroll
                for (int f = 0; f < 2; ++f) {
                    mma16816(acc[wt][f], ahi, bh[2 * f], bh[2 * f + 1]);
                    mma16816(acc[wt][f], ahi, bl[2 * f], bl[2 * f + 1]);
                    mma16816(acc[wt][f], alo, bh[2 * f], bh[2 * f + 1]);
                }
            }
        }
    }

    __syncthreads();  // all A reads done; alias stage buffer onto A region

    // stage: stg[row 16][co 16][w 68] u32 (packed hi|lo), conflict-free
    uint32_t* stg = reinterpret_cast<uint32_t*>(smem);
    {
        int wl = lane >> 2;
        int cl = (lane & 3) * 2;
        #pragma unroll
        for (int wt = 0; wt < 4; ++wt)
            #pragma unroll
            for (int f = 0; f < 2; ++f) {
                int w_a = wt * 16 + wl;
                int co = f * 8 + cl;
                uint32_t* p0 = &stg[(warp * 16 + co) * 68 + w_a];
                p0[0]   = bsplit_u32(acc[wt][f][0]);
                p0[68]  = bsplit_u32(acc[wt][f][1]);
                p0[8]   = bsplit_u32(acc[wt][f][2]);
                p0[76]  = bsplit_u32(acc[wt][f][3]);
            }
    }
    __syncthreads();

    // coalesced store to g_y[bi][co][h][w] (u32 packed)
    uint32_t* yb = g_y + (size_t)bi * (16 * 62 * 62);
    for (int idx = tid; idx < 16 * 16 * 62; idx += 512) {
        int w = idx % 62;
        int co = (idx / 62) & 15;
        int row = idx / 992;
        int hg = r0 + row;
        if (hg < 62)
            yb[(co * 62 + hg) * 62 + w] = stg[(row * 16 + co) * 68 + w];
    }
}

// ---------------------------------------------------------------------------
// Kernel 2: mix via mma.sync bf16 split, warp tile m32 x n64.
// A-fill now loads pre-split u32 y and splits planes with PRMT (no bsplit).
// ---------------------------------------------------------------------------
static constexpr int PITCH = 144;
static constexpr int SM_AHI  = 0;          // 256*144 = 36864
static constexpr int SM_ALO  = 36864;
static constexpr int SM_BHI  = 73728;      // 64*144 = 9216
static constexpr int SM_BLO  = 82944;
static constexpr int SM_BIAS = 92160;
static constexpr int SM_MIX  = 92416;

__global__ __launch_bounds__(256) void mix_mma_kernel(const float* __restrict__ bias,
                                                      float* __restrict__ out) {
    extern __shared__ __align__(16) char smem[];
    uint32_t sb = smem_u32(smem);
    int tid = threadIdx.x;
    int lane = tid & 31;
    int warp = tid >> 5;
    int co = blockIdx.y;
    int b  = blockIdx.z;
    int p_base = blockIdx.x * 256;

    // ---- A = y^T [p][i] hi/lo: one thread per pixel row, all 64 i ----
    // (issued first so the strided LDGs overlap the B-build ALU below)
    {
        int p = tid;
        int pg = p_base + p;
        bool pok = pg < 3844;
        const uint32_t* ybase = g_y + ((size_t)(b * 64) * 16 + co) * 3844 + pg;
        uint32_t base = sb + p * PITCH;
        #pragma unroll
        for (int s = 0; s < 8; ++s) {
            uint32_t v[8];
            #pragma unroll
            for (int e = 0; e < 8; ++e)
                v[e] = pok ? ybase[(size_t)(s * 8 + e) * (16 * 3844)] : 0u;
            uint32_t ph[4], pl[4];
            #pragma unroll
            for (int e = 0; e < 4; ++e) {
                ph[e] = prmt(v[2 * e], v[2 * e + 1], 0x7632u);  // hi halves
                pl[e] = prmt(v[2 * e], v[2 * e + 1], 0x5410u);  // lo halves
            }
            STS128(base + SM_AHI + s * 16, ph[0], ph[1], ph[2], ph[3]);
            STS128(base + SM_ALO + s * 16, pl[0], pl[1], pl[2], pl[3]);
        }
    }

    // ---- B = Wm hi/lo [i][j], row-major, pitch 144B ----
    if (tid < 128) {
        int i = tid & 63;
        int jh = tid >> 6;
        int j0 = jh * 32;
        const float4* src = reinterpret_cast<const float4*>(&g_Wm[i * 64 + j0]);
        uint32_t base = sb + i * PITCH + j0 * 2;
        #pragma unroll
        for (int q = 0; q < 4; ++q) {
            float4 v0 = src[2 * q];
            float4 v1 = src[2 * q + 1];
            uint32_t l0, l1, l2, l3;
            uint32_t h0 = bsplit_pack_hi(v0.x, v0.y, l0);
            uint32_t h1 = bsplit_pack_hi(v0.z, v0.w, l1);
            uint32_t h2 = bsplit_pack_hi(v1.x, v1.y, l2);
            uint32_t h3 = bsplit_pack_hi(v1.z, v1.w, l3);
            STS128(base + SM_BHI + q * 16, h0, h1, h2, h3);
            STS128(base + SM_BLO + q * 16, l0, l1, l2, l3);
        }
    }
    if (tid < 64)
        *reinterpret_cast<float*>(smem + SM_BIAS + tid * 4) = bias[tid];
    __syncthreads();

    float acc[2][8][4];
    #pragma unroll
    for (int mt = 0; mt < 2; ++mt)
        #pragma unroll
        for (int nt = 0; nt < 8; ++nt)
            #pragma unroll
            for (int e = 0; e < 4; ++e) acc[mt][nt][e] = 0.f;

    uint32_t a_row = warp * 32 + (lane & 15);
    uint32_t a_off0 = sb + a_row * PITCH + (lane >> 4) * 16;
    uint32_t a_off1 = a_off0 + 16 * PITCH;
    uint32_t b_kr = (lane & 15);
    uint32_t b_jc = (lane >> 4) * 8;

    #pragma unroll
    for (int k = 0; k < 4; ++k) {
        uint32_t ahi0[4], alo0[4], ahi1[4], alo1[4];
        LDSM_X4(ahi0[0], ahi0[1], ahi0[2], ahi0[3], a_off0 + SM_AHI + k * 32);
        LDSM_X4(alo0[0], alo0[1], alo0[2], alo0[3], a_off0 + SM_ALO + k * 32);
        LDSM_X4(ahi1[0], ahi1[1], ahi1[2], ahi1[3], a_off1 + SM_AHI + k * 32);
        LDSM_X4(alo1[0], alo1[1], alo1[2], alo1[3], a_off1 + SM_ALO + k * 32);

        #pragma unroll
        for (int jp = 0; jp < 4; ++jp) {
            uint32_t baddr = sb + (k * 16 + b_kr) * PITCH + (jp * 16 + b_jc) * 2;
            uint32_t bh[4], bl[4];
            LDSM_X4T(bh[0], bh[1], bh[2], bh[3], baddr + SM_BHI);
            LDSM_X4T(bl[0], bl[1], bl[2], bl[3], baddr + SM_BLO);
            // m-tile 0
            mma16816(acc[0][2 * jp], ahi0, bh[0], bh[1]);
            mma16816(acc[0][2 * jp], ahi0, bl[0], bl[1]);
            mma16816(acc[0][2 * jp], alo0, bh[0], bh[1]);
            mma16816(acc[0][2 * jp + 1], ahi0, bh[2], bh[3]);
            mma16816(acc[0][2 * jp + 1], ahi0, bl[2], bl[3]);
            mma16816(acc[0][2 * jp + 1], alo0, bh[2], bh[3]);
            // m-tile 1 (B fragments reused from registers)
            mma16816(acc[1][2 * jp], ahi1, bh[0], bh[1]);
            mma16816(acc[1][2 * jp], ahi1, bl[0], bl[1]);
            mma16816(acc[1][2 * jp], alo1, bh[0], bh[1]);
            mma16816(acc[1][2 * jp + 1], ahi1, bh[2], bh[3]);
            mma16816(acc[1][2 * jp + 1], ahi1, bl[2], bl[3]);
            mma16816(acc[1][2 * jp + 1], alo1, bh[2], bh[3]);
        }
    }

    size_t rowbase = (size_t)(b * 16 + co) * 3844;
    int jsub = (lane & 3) * 2;

    #pragma unroll
    for (int mt = 0; mt < 2; ++mt) {
        int row0 = warp * 32 + mt * 16 + (lane >> 2);
        int pm0 = p_base + row0;
        int pm1 = pm0 + 8;
        #pragma unroll
        for (int nt = 0; nt < 8; ++nt) {
            int j = nt * 8 + jsub;
            float2 bv = *reinterpret_cast<const float2*>(smem + SM_BIAS + j * 4);
            if (pm0 < 3844)
                *reinterpret_cast<float2*>(&out[(rowbase + pm0) * 64 + j]) =
                    make_float2(acc[mt][nt][0] + bv.x, acc[mt][nt][1] + bv.y);
            if (pm1 < 3844)
                *reinterpret_cast<float2*>(&out[(rowbase + pm1) * 64 + j]) =
                    make_float2(acc[mt][nt][2] + bv.x, acc[mt][nt][3] + bv.y);
        }
    }
}

// ---------------------------------------------------------------------------
extern "C" void kernel_launch(void* const* d_in, const int* in_sizes, int n_in,
                              void* d_out, int out_size) {
    const float* x    = (const float*)d_in[0];
    const float* ker  = (const float*)d_in[1];
    const float* c0   = (const float*)d_in[2];
    const float* c1   = (const float*)d_in[3];
    const float* c2   = (const float*)d_in[4];
    const float* bias = (const float*)d_in[5];
    float* out = (float*)d_out;

    cudaFuncSetAttribute(conv_tc_kernel,
                         cudaFuncAttributeMaxDynamicSharedMemorySize, SM_CONV);
    cudaFuncSetAttribute(mix_mma_kernel,
                         cudaFuncAttributeMaxDynamicSharedMemorySize, SM_MIX);

    conv_tc_kernel<<<2049, 512, SM_CONV>>>(x, ker, c0, c1, c2);
    mix_mma_kernel<<<dim3(16, 16, 8), 256, SM_MIX>>>(bias, out);
}

// round 12
// speedup vs baseline: 1.3315x; 1.3315x over previous
#include <cuda_runtime.h>
#include <cuda_fp16.h>
#include <cstdint>

typedef unsigned long long u64;

// ---------------------------------------------------------------------------
// Tensor-core helpers (baseline PTX: ldmatrix sm_75+, mma.sync sm_80+)
// ---------------------------------------------------------------------------
__device__ __forceinline__ uint32_t smem_u32(const void* p) {
    uint32_t a;
    asm("{ .reg .u64 t; cvta.to.shared.u64 t, %1; cvt.u32.u64 %0, t; }" : "=r"(a) : "l"(p));
    return a;
}

#define LDSM_X4(r0, r1, r2, r3, a) \
    asm volatile("ldmatrix.sync.aligned.m8n8.x4.shared.b16 {%0,%1,%2,%3}, [%4];" \
        : "=r"(r0), "=r"(r1), "=r"(r2), "=r"(r3) : "r"(a))
#define LDSM_X4T(r0, r1, r2, r3, a) \
    asm volatile("ldmatrix.sync.aligned.m8n8.x4.trans.shared.b16 {%0,%1,%2,%3}, [%4];" \
        : "=r"(r0), "=r"(r1), "=r"(r2), "=r"(r3) : "r"(a))

// fp16 x fp16 -> fp32 accum
__device__ __forceinline__ void mma16816(float* d, const uint32_t* a,
                                         uint32_t b0, uint32_t b1) {
    asm volatile(
        "mma.sync.aligned.m16n8k16.row.col.f32.f16.f16.f32 "
        "{%0,%1,%2,%3}, {%4,%5,%6,%7}, {%8,%9}, {%0,%1,%2,%3};"
        : "+f"(d[0]), "+f"(d[1]), "+f"(d[2]), "+f"(d[3])
        : "r"(a[0]), "r"(a[1]), "r"(a[2]), "r"(a[3]), "r"(b0), "r"(b1));
}

// fp16 split: v = hi + lo (hi = rn(v), lo = rn(v - hi)); pack pairs into u32
__device__ __forceinline__ uint32_t hsplit_pack_hi(float v0, float v1, uint32_t& lo) {
    __half h0 = __float2half_rn(v0);
    __half h1 = __float2half_rn(v1);
    __half l0 = __float2half_rn(v0 - __half2float(h0));
    __half l1 = __float2half_rn(v1 - __half2float(h1));
    lo = (uint32_t)__half_as_ushort(l0) | ((uint32_t)__half_as_ushort(l1) << 16);
    return (uint32_t)__half_as_ushort(h0) | ((uint32_t)__half_as_ushort(h1) << 16);
}
__device__ __forceinline__ uint32_t hpack(float v0, float v1) {
    return (uint32_t)__half_as_ushort(__float2half_rn(v0))
         | ((uint32_t)__half_as_ushort(__float2half_rn(v1)) << 16);
}

#define STS128(a, r0, r1, r2, r3) \
    asm volatile("st.shared.v4.b32 [%0], {%1,%2,%3,%4};" :: "r"(a), "r"(r0), "r"(r1), "r"(r2), "r"(r3) : "memory")

// swizzle: flip the 16B slot when bit7 set -> 8 consecutive w pixels (32B
// stride) occupy 8 distinct 16B slots => ldmatrix conflict-free.
#define SWZ(a) ((a) ^ (((a) >> 3) & 0x10))

// ---------------------------------------------------------------------------
// Scratch
// ---------------------------------------------------------------------------
static __device__ float g_Wm[64 * 64];
static __device__ float g_y[512u * 16u * 62u * 62u];

// ---------------------------------------------------------------------------
// Kernel 1: tensor-core conv (fp16 2-term: Ahi*B + Alo*B, B single fp16).
// grid = 512 images x 4 row-strips (+1 Wm block). 512 thr = 16 warps;
// warp = one output row (16-row strips, 18-row halo).
// ---------------------------------------------------------------------------
static constexpr int A_HI = 0;          // 18 * 2176 = 39168
static constexpr int A_LO = 39168;      // 39168
static constexpr int B_SM = 78336;      // 9 * 512 = 4608 (single plane)
static constexpr int SM_CONV = 82944;

__global__ __launch_bounds__(512) void conv_tc_kernel(const float* __restrict__ x,
                                                      const float* __restrict__ ker,
                                                      const float* __restrict__ c0p,
                                                      const float* __restrict__ c1p,
                                                      const float* __restrict__ c2p) {
    extern __shared__ __align__(128) char smem[];
    uint32_t sb = smem_u32(smem);
    int tid = threadIdx.x;

    if (blockIdx.x == 2048) {
        // ---- TT-matrix reconstruction (hidden under the conv wave) ----
        float* s0 = reinterpret_cast<float*>(smem);
        float* s1 = s0 + 128;
        float* s2 = s1 + 1024;
        for (int i = tid; i < 128; i += 512) s0[i] = c0p[i];
        for (int i = tid; i < 1024; i += 512) s1[i] = c1p[i];
        for (int i = tid; i < 128; i += 512) s2[i] = c2p[i];
        __syncthreads();
        for (int e = tid; e < 4096; e += 512) {
            int i = e >> 6, j = e & 63;
            int i1 = i >> 4, i2 = (i >> 2) & 3, i3 = i & 3;
            int j1 = j >> 4, j2 = (j >> 2) & 3, j3 = j & 3;
            float s = 0.f;
            #pragma unroll
            for (int r1 = 0; r1 < 8; ++r1) {
                float a = s0[(i1 * 4 + j1) * 8 + r1];
                float t = 0.f;
                #pragma unroll
                for (int r2 = 0; r2 < 8; ++r2)
                    t += s1[((r1 * 4 + i2) * 4 + j2) * 8 + r2] * s2[(r2 * 4 + i3) * 4 + j3];
                s = fmaf(a, t, s);
            }
            g_Wm[e] = s;
        }
        return;
    }

    int bi = blockIdx.x >> 2;
    int strip = blockIdx.x & 3;
    int r0 = strip * 16;

    // zero ONLY the w=64..67 pad slots (both A buffers, 18 rows)
    for (int idx = tid; idx < 288; idx += 512) {
        int bsel  = idx & 1;
        int chunk = (idx >> 1) & 1;
        int w  = 64 + ((idx >> 2) & 3);
        int rr = idx >> 4;                 // 0..17
        uint32_t raw = (uint32_t)rr * 2176 + w * 32 + chunk * 16;
        uint32_t a = SWZ(raw) + (bsel ? A_LO : A_HI);
        STS128(sb + a, 0u, 0u, 0u, 0u);
    }

    // B fill: ker flat [co][cin][kh][kw] -> [tap][cin][co] single fp16
    for (int idx = tid; idx < 2304; idx += 512) {
        int co = idx / 144, rem = idx % 144;
        int cin = rem / 9, kk = rem % 9;
        uint32_t raw = (uint32_t)kk * 512 + cin * 32 + co * 2;
        *reinterpret_cast<unsigned short*>(smem + B_SM + SWZ(raw)) =
            __half_as_ushort(__float2half_rn(ker[idx]));
    }

    // A fill: thread = (row, w); pack 16 cin -> 2x STS.128 per buffer.
    const float* xb = x + (size_t)bi * (16 * 64 * 64);
    for (int idx = tid; idx < 1152; idx += 512) {
        int w  = idx & 63;
        int rr = idx >> 6;                 // 0..17
        int rg = r0 + rr; if (rg > 63) rg = 63;
        const float* src = xb + rg * 64 + w;
        uint32_t ph[8], pl[8];
        #pragma unroll
        for (int e = 0; e < 8; ++e) {
            float v0 = src[(size_t)(2 * e) * 4096];
            float v1 = src[(size_t)(2 * e + 1) * 4096];
            ph[e] = hsplit_pack_hi(v0, v1, pl[e]);
        }
        uint32_t raw0 = (uint32_t)rr * 2176 + w * 32;
        uint32_t a0 = SWZ(raw0);
        uint32_t a1 = SWZ(raw0 + 16);
        STS128(sb + A_HI + a0, ph[0], ph[1], ph[2], ph[3]);
        STS128(sb + A_HI + a1, ph[4], ph[5], ph[6], ph[7]);
        STS128(sb + A_LO + a0, pl[0], pl[1], pl[2], pl[3]);
        STS128(sb + A_LO + a1, pl[4], pl[5], pl[6], pl[7]);
    }
    __syncthreads();

    int lane = tid & 31;
    int warp = tid >> 5;          // output row within strip (0..15)
    int h = r0 + warp;

    float acc[4][2][4];
    #pragma unroll
    for (int wt = 0; wt < 4; ++wt)
        #pragma unroll
        for (int f = 0; f < 2; ++f)
            #pragma unroll
            for (int e = 0; e < 4; ++e) acc[wt][f][e] = 0.f;

    int arow = lane & 15;
    int khalf = (lane >> 4) * 16;

    #pragma unroll
    for (int kh = 0; kh < 3; ++kh) {
        #pragma unroll
        for (int kw = 0; kw < 3; ++kw) {
            int tap = kh * 3 + kw;
            uint32_t brw = (uint32_t)tap * 512 + arow * 32 + khalf;
            uint32_t bh[4];
            LDSM_X4T(bh[0], bh[1], bh[2], bh[3], sb + B_SM + SWZ(brw));

            uint32_t rbase = (uint32_t)(warp + kh) * 2176;
            #pragma unroll
            for (int wt = 0; wt < 4; ++wt) {
                uint32_t araw = rbase + (wt * 16 + arow + kw) * 32 + khalf;
                uint32_t aaddr = sb + SWZ(araw);
                uint32_t ahi[4], alo[4];
                LDSM_X4(ahi[0], ahi[1], ahi[2], ahi[3], aaddr + A_HI);
                LDSM_X4(alo[0], alo[1], alo[2], alo[3], aaddr + A_LO);
                #pragma unroll
                for (int f = 0; f < 2; ++f) {
                    mma16816(acc[wt][f], ahi, bh[2 * f], bh[2 * f + 1]);
                    mma16816(acc[wt][f], alo, bh[2 * f], bh[2 * f + 1]);
                }
            }
        }
    }

    __syncthreads();  // all A reads done; alias stage buffer onto A region

    // stage: stg[row 16][co 16][w 68] floats = 69632 B (fits in A region)
    float* stg = reinterpret_cast<float*>(smem);
    {
        int wl = lane >> 2;
        int cl = (lane & 3) * 2;
        #pragma unroll
        for (int wt = 0; wt < 4; ++wt)
            #pragma unroll
            for (int f = 0; f < 2; ++f) {
                int w_a = wt * 16 + wl;
                int co = f * 8 + cl;
                float* p0 = &stg[(warp * 16 + co) * 68 + w_a];
                p0[0]   = acc[wt][f][0];
                p0[68]  = acc[wt][f][1];
                p0[8]   = acc[wt][f][2];
                p0[76]  = acc[wt][f][3];
            }
    }
    __syncthreads();

    // coalesced store to g_y[bi][co][h][w]
    float* yb = g_y + (size_t)bi * (16 * 62 * 62);
    for (int idx = tid; idx < 16 * 16 * 62; idx += 512) {
        int w = idx % 62;
        int co = (idx / 62) & 15;
        int row = idx / 992;
        int hg = r0 + row;
        if (hg < 62)
            yb[(co * 62 + hg) * 62 + w] = stg[(row * 16 + co) * 68 + w];
    }
}

// ---------------------------------------------------------------------------
// Kernel 2: mix via mma.sync fp16 2-term, warp tile m32 x n64.
// Block = 256 pixels x 64 j; grid (16, 16 co, 8 b); 256 threads = 8 warps.
// ---------------------------------------------------------------------------
static constexpr int PITCH = 144;
static constexpr int SM_AHI  = 0;          // 256*144 = 36864
static constexpr int SM_ALO  = 36864;
static constexpr int SM_BHI  = 73728;      // 64*144 = 9216 (single plane)
static constexpr int SM_BIAS = 82944;
static constexpr int SM_MIX  = 83200;

__global__ __launch_bounds__(256) void mix_mma_kernel(const float* __restrict__ bias,
                                                      float* __restrict__ out) {
    extern __shared__ __align__(16) char smem[];
    uint32_t sb = smem_u32(smem);
    int tid = threadIdx.x;
    int lane = tid & 31;
    int warp = tid >> 5;
    int co = blockIdx.y;
    int b  = blockIdx.z;
    int p_base = blockIdx.x * 256;

    // ---- B = Wm single fp16 [i][j], row-major, pitch 144B ----
    if (tid < 128) {
        int i = tid & 63;
        int jh = tid >> 6;
        int j0 = jh * 32;
        const float4* src = reinterpret_cast<const float4*>(&g_Wm[i * 64 + j0]);
        uint32_t base = sb + i * PITCH + j0 * 2;
        #pragma unroll
        for (int q = 0; q < 4; ++q) {
            float4 v0 = src[2 * q];
            float4 v1 = src[2 * q + 1];
            uint32_t h0 = hpack(v0.x, v0.y);
            uint32_t h1 = hpack(v0.z, v0.w);
            uint32_t h2 = hpack(v1.x, v1.y);
            uint32_t h3 = hpack(v1.z, v1.w);
            STS128(base + SM_BHI + q * 16, h0, h1, h2, h3);
        }
    }
    if (tid < 64)
        *reinterpret_cast<float*>(smem + SM_BIAS + tid * 4) = bias[tid];

    // ---- A = y^T [p][i] fp16 hi/lo: one thread per pixel row, all 64 i ----
    {
        int p = tid;
        int pg = p_base + p;
        bool pok = pg < 3844;
        const float* ybase = g_y + ((size_t)(b * 64) * 16 + co) * 3844 + pg;
        uint32_t base = sb + p * PITCH;
        #pragma unroll
        for (int s = 0; s < 8; ++s) {
            float v[8];
            #pragma unroll
            for (int e = 0; e < 8; ++e)
                v[e] = pok ? ybase[(size_t)(s * 8 + e) * (16 * 3844)] : 0.f;
            uint32_t l0, l1, l2, l3;
            uint32_t h0 = hsplit_pack_hi(v[0], v[1], l0);
            uint32_t h1 = hsplit_pack_hi(v[2], v[3], l1);
            uint32_t h2 = hsplit_pack_hi(v[4], v[5], l2);
            uint32_t h3 = hsplit_pack_hi(v[6], v[7], l3);
            STS128(base + SM_AHI + s * 16, h0, h1, h2, h3);
            STS128(base + SM_ALO + s * 16, l0, l1, l2, l3);
        }
    }
    __syncthreads();

    float acc[2][8][4];
    #pragma unroll
    for (int mt = 0; mt < 2; ++mt)
        #pragma unroll
        for (int nt = 0; nt < 8; ++nt)
            #pragma unroll
            for (int e = 0; e < 4; ++e) acc[mt][nt][e] = 0.f;

    uint32_t a_row = warp * 32 + (lane & 15);
    uint32_t a_off0 = sb + a_row * PITCH + (lane >> 4) * 16;
    uint32_t a_off1 = a_off0 + 16 * PITCH;
    uint32_t b_kr = (lane & 15);
    uint32_t b_jc = (lane >> 4) * 8;

    #pragma unroll
    for (int k = 0; k < 4; ++k) {
        uint32_t ahi0[4], alo0[4], ahi1[4], alo1[4];
        LDSM_X4(ahi0[0], ahi0[1], ahi0[2], ahi0[3], a_off0 + SM_AHI + k * 32);
        LDSM_X4(alo0[0], alo0[1], alo0[2], alo0[3], a_off0 + SM_ALO + k * 32);
        LDSM_X4(ahi1[0], ahi1[1], ahi1[2], ahi1[3], a_off1 + SM_AHI + k * 32);
        LDSM_X4(alo1[0], alo1[1], alo1[2], alo1[3], a_off1 + SM_ALO + k * 32);

        #pragma unroll
        for (int jp = 0; jp < 4; ++jp) {
            uint32_t baddr = sb + (k * 16 + b_kr) * PITCH + (jp * 16 + b_jc) * 2;
            uint32_t bh[4];
            LDSM_X4T(bh[0], bh[1], bh[2], bh[3], baddr + SM_BHI);
            // m-tile 0
            mma16816(acc[0][2 * jp], ahi0, bh[0], bh[1]);
            mma16816(acc[0][2 * jp], alo0, bh[0], bh[1]);
            mma16816(acc[0][2 * jp + 1], ahi0, bh[2], bh[3]);
            mma16816(acc[0][2 * jp + 1], alo0, bh[2], bh[3]);
            // m-tile 1 (B fragments reused from registers)
            mma16816(acc[1][2 * jp], ahi1, bh[0], bh[1]);
            mma16816(acc[1][2 * jp], alo1, bh[0], bh[1]);
            mma16816(acc[1][2 * jp + 1], ahi1, bh[2], bh[3]);
            mma16816(acc[1][2 * jp + 1], alo1, bh[2], bh[3]);
        }
    }

    size_t rowbase = (size_t)(b * 16 + co) * 3844;
    int jsub = (lane & 3) * 2;

    #pragma unroll
    for (int mt = 0; mt < 2; ++mt) {
        int row0 = warp * 32 + mt * 16 + (lane >> 2);
        int pm0 = p_base + row0;
        int pm1 = pm0 + 8;
        #pragma unroll
        for (int nt = 0; nt < 8; ++nt) {
            int j = nt * 8 + jsub;
            float2 bv = *reinterpret_cast<const float2*>(smem + SM_BIAS + j * 4);
            if (pm0 < 3844)
                *reinterpret_cast<float2*>(&out[(rowbase + pm0) * 64 + j]) =
                    make_float2(acc[mt][nt][0] + bv.x, acc[mt][nt][1] + bv.y);
            if (pm1 < 3844)
                *reinterpret_cast<float2*>(&out[(rowbase + pm1) * 64 + j]) =
                    make_float2(acc[mt][nt][2] + bv.x, acc[mt][nt][3] + bv.y);
        }
    }
}

// ---------------------------------------------------------------------------
extern "C" void kernel_launch(void* const* d_in, const int* in_sizes, int n_in,
                              void* d_out, int out_size) {
    const float* x    = (const float*)d_in[0];
    const float* ker  = (const float*)d_in[1];
    const float* c0   = (const float*)d_in[2];
    const float* c1   = (const float*)d_in[3];
    const float* c2   = (const float*)d_in[4];
    const float* bias = (const float*)d_in[5];
    float* out = (float*)d_out;

    cudaFuncSetAttribute(conv_tc_kernel,
                         cudaFuncAttributeMaxDynamicSharedMemorySize, SM_CONV);
    cudaFuncSetAttribute(mix_mma_kernel,
                         cudaFuncAttributeMaxDynamicSharedMemorySize, SM_MIX);

    conv_tc_kernel<<<2049, 512, SM_CONV>>>(x, ker, c0, c1, c2);
    mix_mma_kernel<<<dim3(16, 16, 8), 256, SM_MIX>>>(bias, out);
}

// round 15
// speedup vs baseline: 1.4545x; 1.0924x over previous
#include <cuda_runtime.h>
#include <cuda_fp16.h>
#include <cstdint>

typedef unsigned long long u64;

// ---------------------------------------------------------------------------
// Tensor-core helpers (baseline PTX: ldmatrix sm_75+, mma.sync sm_80+)
// ---------------------------------------------------------------------------
__device__ __forceinline__ uint32_t smem_u32(const void* p) {
    uint32_t a;
    asm("{ .reg .u64 t; cvta.to.shared.u64 t, %1; cvt.u32.u64 %0, t; }" : "=r"(a) : "l"(p));
    return a;
}

#define LDSM_X4(r0, r1, r2, r3, a) \
    asm volatile("ldmatrix.sync.aligned.m8n8.x4.shared.b16 {%0,%1,%2,%3}, [%4];" \
        : "=r"(r0), "=r"(r1), "=r"(r2), "=r"(r3) : "r"(a))
#define LDSM_X4T(r0, r1, r2, r3, a) \
    asm volatile("ldmatrix.sync.aligned.m8n8.x4.trans.shared.b16 {%0,%1,%2,%3}, [%4];" \
        : "=r"(r0), "=r"(r1), "=r"(r2), "=r"(r3) : "r"(a))

// fp16 x fp16 -> fp32 accum
__device__ __forceinline__ void mma16816(float* d, const uint32_t* a,
                                         uint32_t b0, uint32_t b1) {
    asm volatile(
        "mma.sync.aligned.m16n8k16.row.col.f32.f16.f16.f32 "
        "{%0,%1,%2,%3}, {%4,%5,%6,%7}, {%8,%9}, {%0,%1,%2,%3};"
        : "+f"(d[0]), "+f"(d[1]), "+f"(d[2]), "+f"(d[3])
        : "r"(a[0]), "r"(a[1]), "r"(a[2]), "r"(a[3]), "r"(b0), "r"(b1));
}

// fp16 split: v = hi + lo; pack pairs into u32
__device__ __forceinline__ uint32_t hsplit_pack_hi(float v0, float v1, uint32_t& lo) {
    __half h0 = __float2half_rn(v0);
    __half h1 = __float2half_rn(v1);
    __half l0 = __float2half_rn(v0 - __half2float(h0));
    __half l1 = __float2half_rn(v1 - __half2float(h1));
    lo = (uint32_t)__half_as_ushort(l0) | ((uint32_t)__half_as_ushort(l1) << 16);
    return (uint32_t)__half_as_ushort(h0) | ((uint32_t)__half_as_ushort(h1) << 16);
}
__device__ __forceinline__ uint32_t hpack(float v0, float v1) {
    return (uint32_t)__half_as_ushort(__float2half_rn(v0))
         | ((uint32_t)__half_as_ushort(__float2half_rn(v1)) << 16);
}

#define STS128(a, r0, r1, r2, r3) \
    asm volatile("st.shared.v4.b32 [%0], {%1,%2,%3,%4};" :: "r"(a), "r"(r0), "r"(r1), "r"(r2), "r"(r3) : "memory")

// swizzle: flip the 16B slot when bit7 set -> 8 consecutive w pixels (32B
// stride) occupy 8 distinct 16B slots => ldmatrix conflict-free.
#define SWZ(a) ((a) ^ (((a) >> 3) & 0x10))

// ---------------------------------------------------------------------------
// Scratch.  g_y is fp16 now (63 MB instead of 126 MB).
// ---------------------------------------------------------------------------
static __device__ float g_Wm[64 * 64];
static __device__ __half g_y[512u * 16u * 62u * 62u];

// ---------------------------------------------------------------------------
// Kernel 1: tensor-core conv (fp16 2-term A, single-fp16 B).
// grid = 512 images x 4 row-strips (+1 Wm block). 512 thr = 16 warps;
// warp = one output row (16-row strips, 18-row halo).
// Epilogue stores y as fp16 (u16 stage + coalesced u16 stores).
// ---------------------------------------------------------------------------
static constexpr int A_HI = 0;          // 18 * 2176 = 39168
static constexpr int A_LO = 39168;      // 39168
static constexpr int B_SM = 78336;      // 9 * 512 = 4608 (single plane)
static constexpr int SM_CONV = 82944;

__global__ __launch_bounds__(512) void conv_tc_kernel(const float* __restrict__ x,
                                                      const float* __restrict__ ker,
                                                      const float* __restrict__ c0p,
                                                      const float* __restrict__ c1p,
                                                      const float* __restrict__ c2p) {
    extern __shared__ __align__(128) char smem[];
    uint32_t sb = smem_u32(smem);
    int tid = threadIdx.x;

    if (blockIdx.x == 2048) {
        // ---- TT-matrix reconstruction (hidden under the conv wave) ----
        float* s0 = reinterpret_cast<float*>(smem);
        float* s1 = s0 + 128;
        float* s2 = s1 + 1024;
        for (int i = tid; i < 128; i += 512) s0[i] = c0p[i];
        for (int i = tid; i < 1024; i += 512) s1[i] = c1p[i];
        for (int i = tid; i < 128; i += 512) s2[i] = c2p[i];
        __syncthreads();
        for (int e = tid; e < 4096; e += 512) {
            int i = e >> 6, j = e & 63;
            int i1 = i >> 4, i2 = (i >> 2) & 3, i3 = i & 3;
            int j1 = j >> 4, j2 = (j >> 2) & 3, j3 = j & 3;
            float s = 0.f;
            #pragma unroll
            for (int r1 = 0; r1 < 8; ++r1) {
                float a = s0[(i1 * 4 + j1) * 8 + r1];
                float t = 0.f;
                #pragma unroll
                for (int r2 = 0; r2 < 8; ++r2)
                    t += s1[((r1 * 4 + i2) * 4 + j2) * 8 + r2] * s2[(r2 * 4 + i3) * 4 + j3];
                s = fmaf(a, t, s);
            }
            g_Wm[e] = s;
        }
        return;
    }

    int bi = blockIdx.x >> 2;
    int strip = blockIdx.x & 3;
    int r0 = strip * 16;

    // zero ONLY the w=64..67 pad slots (both A buffers, 18 rows)
    for (int idx = tid; idx < 288; idx += 512) {
        int bsel  = idx & 1;
        int chunk = (idx >> 1) & 1;
        int w  = 64 + ((idx >> 2) & 3);
        int rr = idx >> 4;                 // 0..17
        uint32_t raw = (uint32_t)rr * 2176 + w * 32 + chunk * 16;
        uint32_t a = SWZ(raw) + (bsel ? A_LO : A_HI);
        STS128(sb + a, 0u, 0u, 0u, 0u);
    }

    // B fill: ker flat [co][cin][kh][kw] -> [tap][cin][co] single fp16
    for (int idx = tid; idx < 2304; idx += 512) {
        int co = idx / 144, rem = idx % 144;
        int cin = rem / 9, kk = rem % 9;
        uint32_t raw = (uint32_t)kk * 512 + cin * 32 + co * 2;
        *reinterpret_cast<unsigned short*>(smem + B_SM + SWZ(raw)) =
            __half_as_ushort(__float2half_rn(ker[idx]));
    }

    // A fill: thread = (row, w); pack 16 cin -> 2x STS.128 per buffer.
    const float* xb = x + (size_t)bi * (16 * 64 * 64);
    for (int idx = tid; idx < 1152; idx += 512) {
        int w  = idx & 63;
        int rr = idx >> 6;                 // 0..17
        int rg = r0 + rr; if (rg > 63) rg = 63;
        const float* src = xb + rg * 64 + w;
        uint32_t ph[8], pl[8];
        #pragma unroll
        for (int e = 0; e < 8; ++e) {
            float v0 = src[(size_t)(2 * e) * 4096];
            float v1 = src[(size_t)(2 * e + 1) * 4096];
            ph[e] = hsplit_pack_hi(v0, v1, pl[e]);
        }
        uint32_t raw0 = (uint32_t)rr * 2176 + w * 32;
        uint32_t a0 = SWZ(raw0);
        uint32_t a1 = SWZ(raw0 + 16);
        STS128(sb + A_HI + a0, ph[0], ph[1], ph[2], ph[3]);
        STS128(sb + A_HI + a1, ph[4], ph[5], ph[6], ph[7]);
        STS128(sb + A_LO + a0, pl[0], pl[1], pl[2], pl[3]);
        STS128(sb + A_LO + a1, pl[4], pl[5], pl[6], pl[7]);
    }
    __syncthreads();

    int lane = tid & 31;
    int warp = tid >> 5;          // output row within strip (0..15)
    int h = r0 + warp;

    float acc[4][2][4];
    #pragma unroll
    for (int wt = 0; wt < 4; ++wt)
        #pragma unroll
        for (int f = 0; f < 2; ++f)
            #pragma unroll
            for (int e = 0; e < 4; ++e) acc[wt][f][e] = 0.f;

    int arow = lane & 15;
    int khalf = (lane >> 4) * 16;

    #pragma unroll
    for (int kh = 0; kh < 3; ++kh) {
        #pragma unroll
        for (int kw = 0; kw < 3; ++kw) {
            int tap = kh * 3 + kw;
            uint32_t brw = (uint32_t)tap * 512 + arow * 32 + khalf;
            uint32_t bh[4];
            LDSM_X4T(bh[0], bh[1], bh[2], bh[3], sb + B_SM + SWZ(brw));

            uint32_t rbase = (uint32_t)(warp + kh) * 2176;
            #pragma unroll
            for (int wt = 0; wt < 4; ++wt) {
                uint32_t araw = rbase + (wt * 16 + arow + kw) * 32 + khalf;
                uint32_t aaddr = sb + SWZ(araw);
                uint32_t ahi[4], alo[4];
                LDSM_X4(ahi[0], ahi[1], ahi[2], ahi[3], aaddr + A_HI);
                LDSM_X4(alo[0], alo[1], alo[2], alo[3], aaddr + A_LO);
                #pragma unroll
                for (int f = 0; f < 2; ++f) {
                    mma16816(acc[wt][f], ahi, bh[2 * f], bh[2 * f + 1]);
                    mma16816(acc[wt][f], alo, bh[2 * f], bh[2 * f + 1]);
                }
            }
        }
    }

    __syncthreads();  // all A reads done; alias stage buffer onto A region

    // stage: stg[row 16][co 16][w 68] u16 = 34816 B (fits in A region)
    unsigned short* stg = reinterpret_cast<unsigned short*>(smem);
    {
        int wl = lane >> 2;
        int cl = (lane & 3) * 2;
        #pragma unroll
        for (int wt = 0; wt < 4; ++wt)
            #pragma unroll
            for (int f = 0; f < 2; ++f) {
                int w_a = wt * 16 + wl;
                int co = f * 8 + cl;
                unsigned short* p0 = &stg[(warp * 16 + co) * 68 + w_a];
                p0[0]   = __half_as_ushort(__float2half_rn(acc[wt][f][0]));
                p0[68]  = __half_as_ushort(__float2half_rn(acc[wt][f][1]));
                p0[8]   = __half_as_ushort(__float2half_rn(acc[wt][f][2]));
                p0[76]  = __half_as_ushort(__float2half_rn(acc[wt][f][3]));
            }
    }
    __syncthreads();

    // coalesced u16 store to g_y[bi][co][h][w]
    __half* yb = g_y + (size_t)bi * (16 * 62 * 62);
    for (int idx = tid; idx < 16 * 16 * 62; idx += 512) {
        int w = idx % 62;
        int co = (idx / 62) & 15;
        int row = idx / 992;
        int hg = r0 + row;
        if (hg < 62)
            yb[(co * 62 + hg) * 62 + w] = __ushort_as_half(stg[(row * 16 + co) * 68 + w]);
    }
}

// ---------------------------------------------------------------------------
// Kernel 2: mix via mma.sync, single-fp16 A and B, warp tile m32 x n64.
// Block = 256 pixels x 64 j; grid (16, 16 co, 8 b); 256 threads = 8 warps.
// Per k-step: 6 LDSM + 16 MMA (was 12 + 32).
// ---------------------------------------------------------------------------
static constexpr int PITCH = 144;
static constexpr int SM_A    = 0;          // 256*144 = 36864
static constexpr int SM_B    = 36864;      // 64*144 = 9216
static constexpr int SM_BIAS = 46080;
static constexpr int SM_MIX  = 46336;

__global__ __launch_bounds__(256) void mix_mma_kernel(const float* __restrict__ bias,
                                                      float* __restrict__ out) {
    extern __shared__ __align__(16) char smem[];
    uint32_t sb = smem_u32(smem);
    int tid = threadIdx.x;
    int lane = tid & 31;
    int warp = tid >> 5;
    int co = blockIdx.y;
    int b  = blockIdx.z;
    int p_base = blockIdx.x * 256;

    // ---- A = y^T [p][i] fp16: one thread per pixel row, all 64 i ----
    {
        int p = tid;
        int pg = p_base + p;
        bool pok = pg < 3844;
        const __half* ybase = g_y + ((size_t)(b * 64) * 16 + co) * 3844 + pg;
        uint32_t base = sb + SM_A + p * PITCH;
        #pragma unroll
        for (int s = 0; s < 8; ++s) {
            uint32_t u[4];
            #pragma unroll
            for (int e = 0; e < 4; ++e) {
                uint32_t a0 = pok ? (uint32_t)__half_as_ushort(ybase[(size_t)(s * 8 + 2 * e) * (16 * 3844)]) : 0u;
                uint32_t a1 = pok ? (uint32_t)__half_as_ushort(ybase[(size_t)(s * 8 + 2 * e + 1) * (16 * 3844)]) : 0u;
                u[e] = a0 | (a1 << 16);
            }
            STS128(base + s * 16, u[0], u[1], u[2], u[3]);
        }
    }

    // ---- B = Wm single fp16 [i][j], row-major, pitch 144B ----
    if (tid < 128) {
        int i = tid & 63;
        int jh = tid >> 6;
        int j0 = jh * 32;
        const float4* src = reinterpret_cast<const float4*>(&g_Wm[i * 64 + j0]);
        uint32_t base = sb + SM_B + i * PITCH + j0 * 2;
        #pragma unroll
        for (int q = 0; q < 4; ++q) {
            float4 v0 = src[2 * q];
            float4 v1 = src[2 * q + 1];
            STS128(base + q * 16, hpack(v0.x, v0.y), hpack(v0.z, v0.w),
                   hpack(v1.x, v1.y), hpack(v1.z, v1.w));
        }
    }
    if (tid < 64)
        *reinterpret_cast<float*>(smem + SM_BIAS + tid * 4) = bias[tid];
    __syncthreads();

    float acc[2][8][4];
    #pragma unroll
    for (int mt = 0; mt < 2; ++mt)
        #pragma unroll
        for (int nt = 0; nt < 8; ++nt)
            #pragma unroll
            for (int e = 0; e < 4; ++e) acc[mt][nt][e] = 0.f;

    uint32_t a_row = warp * 32 + (lane & 15);
    uint32_t a_off0 = sb + SM_A + a_row * PITCH + (lane >> 4) * 16;
    uint32_t a_off1 = a_off0 + 16 * PITCH;
    uint32_t b_kr = (lane & 15);
    uint32_t b_jc = (lane >> 4) * 8;

    #pragma unroll
    for (int k = 0; k < 4; ++k) {
        uint32_t a0[4], a1[4];
        LDSM_X4(a0[0], a0[1], a0[2], a0[3], a_off0 + k * 32);
        LDSM_X4(a1[0], a1[1], a1[2], a1[3], a_off1 + k * 32);

        #pragma unroll
        for (int jp = 0; jp < 4; ++jp) {
            uint32_t baddr = sb + SM_B + (k * 16 + b_kr) * PITCH + (jp * 16 + b_jc) * 2;
            uint32_t bh[4];
            LDSM_X4T(bh[0], bh[1], bh[2], bh[3], baddr);
            mma16816(acc[0][2 * jp],     a0, bh[0], bh[1]);
            mma16816(acc[0][2 * jp + 1], a0, bh[2], bh[3]);
            mma16816(acc[1][2 * jp],     a1, bh[0], bh[1]);
            mma16816(acc[1][2 * jp + 1], a1, bh[2], bh[3]);
        }
    }

    size_t rowbase = (size_t)(b * 16 + co) * 3844;
    int jsub = (lane & 3) * 2;

    #pragma unroll
    for (int mt = 0; mt < 2; ++mt) {
        int row0 = warp * 32 + mt * 16 + (lane >> 2);
        int pm0 = p_base + row0;
        int pm1 = pm0 + 8;
        #pragma unroll
        for (int nt = 0; nt < 8; ++nt) {
            int j = nt * 8 + jsub;
            float2 bv = *reinterpret_cast<const float2*>(smem + SM_BIAS + j * 4);
            if (pm0 < 3844)
                *reinterpret_cast<float2*>(&out[(rowbase + pm0) * 64 + j]) =
                    make_float2(acc[mt][nt][0] + bv.x, acc[mt][nt][1] + bv.y);
            if (pm1 < 3844)
                *reinterpret_cast<float2*>(&out[(rowbase + pm1) * 64 + j]) =
                    make_float2(acc[mt][nt][2] + bv.x, acc[mt][nt][3] + bv.y);
        }
    }
}

// ---------------------------------------------------------------------------
extern "C" void kernel_launch(void* const* d_in, const int* in_sizes, int n_in,
                              void* d_out, int out_size) {
    const float* x    = (const float*)d_in[0];
    const float* ker  = (const float*)d_in[1];
    const float* c0   = (const float*)d_in[2];
    const float* c1   = (const float*)d_in[3];
    const float* c2   = (const float*)d_in[4];
    const float* bias = (const float*)d_in[5];
    float* out = (float*)d_out;

    cudaFuncSetAttribute(conv_tc_kernel,
                         cudaFuncAttributeMaxDynamicSharedMemorySize, SM_CONV);
    cudaFuncSetAttribute(mix_mma_kernel,
                         cudaFuncAttributeMaxDynamicSharedMemorySize, SM_MIX);

    conv_tc_kernel<<<2049, 512, SM_CONV>>>(x, ker, c0, c1, c2);
    mix_mma_kernel<<<dim3(16, 16, 8), 256, SM_MIX>>>(bias, out);
}